// round 5
// baseline (speedup 1.0000x reference)
#include <cuda_runtime.h>

// Problem constants (fixed by the reference).
#define BB   64
#define TT   512
#define VV   96
#define HH   1024
#define NCTA 128   // 8 k-chunks x 16 column tiles, all co-resident (1 CTA/SM, 48KB smem)

// ---------------------------------------------------------------------------
// Scratch (device globals: allocation-free per harness rules)
// ---------------------------------------------------------------------------
__device__ float g_xproj[(size_t)BB * TT * HH];     // x @ Wxh + bh, [b][t][h]
__device__ float g_hs   [(size_t)BB * TT * HH];     // hidden states, [b][t][h]
__device__ float g_partial[8 * BB * HH];            // split-K partials [kc][b][j]
__device__ unsigned g_cnt = 0;
__device__ volatile unsigned g_gen = 0;

// ---------------------------------------------------------------------------
// Global software barrier (R3-proven). Tight volatile spin (no nanosleep):
// with 1 CTA/SM the spinner starves nobody, and poll latency = one L2 round
// trip instead of 64ns quantization.
// ---------------------------------------------------------------------------
__device__ __forceinline__ void gbar()
{
    __syncthreads();
    if (threadIdx.x == 0) {
        __threadfence();                      // release prior global stores
        unsigned g = g_gen;
        if (atomicAdd(&g_cnt, 1u) == NCTA - 1) {
            g_cnt = 0;
            __threadfence();
            g_gen = g + 1;
        } else {
            while (g_gen == g) {}
        }
        __threadfence();                      // acquire
    }
    __syncthreads();
}

// ---------------------------------------------------------------------------
// Packed fp32x2 helpers (Blackwell FFMA2 — identical IEEE fp32 numerics).
// ---------------------------------------------------------------------------
__device__ __forceinline__ unsigned long long splat2(float a)
{
    unsigned long long r;
    asm("mov.b64 %0, {%1, %1};" : "=l"(r) : "f"(a));
    return r;
}
__device__ __forceinline__ void ffma2(unsigned long long& d,
                                      unsigned long long a, unsigned long long b)
{
    asm("fma.rn.f32x2 %0, %1, %2, %0;" : "+l"(d) : "l"(a), "l"(b));
}
union F4U {
    float4 f;
    unsigned long long u[2];
};

// ---------------------------------------------------------------------------
// Kernel 1: xproj[r][j] = sum_v x[r][v] * Wxh[v][j] + bh[j]   (r = b*T + t)
// (unchanged from R3 — already near the fp32 ceiling for its size)
// ---------------------------------------------------------------------------
__global__ void __launch_bounds__(256) xproj_kernel(const float* __restrict__ x,
                                                    const float* __restrict__ Wxh,
                                                    const float* __restrict__ bh)
{
    __shared__ float sa[64][36];
    __shared__ float sw[32][64];

    const int tid = threadIdx.x;
    const int tx  = tid & 15;
    const int ty  = tid >> 4;
    const size_t row0 = (size_t)blockIdx.y * 64;
    const int jt  = blockIdx.x;

    float acc[4][4] = {};

    #pragma unroll 1
    for (int K0 = 0; K0 < 96; K0 += 32) {
        #pragma unroll
        for (int i = 0; i < 2; ++i) {
            int idx = tid + i * 256;
            int r = idx >> 3, k4 = (idx & 7) * 4;
            float4 v = *(const float4*)(x + (row0 + r) * 96 + K0 + k4);
            *(float4*)&sa[r][k4] = v;
        }
        #pragma unroll
        for (int i = 0; i < 2; ++i) {
            int idx = tid + i * 256;
            int kk = idx >> 4, j4 = (idx & 15) * 4;
            float4 v = *(const float4*)(Wxh + (size_t)(K0 + kk) * HH + jt * 64 + j4);
            *(float4*)&sw[kk][j4] = v;
        }
        __syncthreads();
        #pragma unroll 4
        for (int k = 0; k < 32; k += 4) {
            float ha[4][4], wa[4][4];
            #pragma unroll
            for (int i = 0; i < 4; ++i) {
                float4 v = *(const float4*)&sa[ty * 4 + i][k];
                ha[i][0] = v.x; ha[i][1] = v.y; ha[i][2] = v.z; ha[i][3] = v.w;
            }
            #pragma unroll
            for (int kk = 0; kk < 4; ++kk) {
                float4 v = *(const float4*)&sw[k + kk][tx * 4];
                wa[kk][0] = v.x; wa[kk][1] = v.y; wa[kk][2] = v.z; wa[kk][3] = v.w;
            }
            #pragma unroll
            for (int kk = 0; kk < 4; ++kk)
                #pragma unroll
                for (int i = 0; i < 4; ++i)
                    #pragma unroll
                    for (int j = 0; j < 4; ++j)
                        acc[i][j] += ha[i][kk] * wa[kk][j];
        }
        __syncthreads();
    }

    float4 bv = *(const float4*)(bh + jt * 64 + tx * 4);
    #pragma unroll
    for (int i = 0; i < 4; ++i) {
        float4 v = make_float4(acc[i][0] + bv.x, acc[i][1] + bv.y,
                               acc[i][2] + bv.z, acc[i][3] + bv.w);
        *(float4*)&g_xproj[(row0 + ty * 4 + i) * HH + jt * 64 + tx * 4] = v;
    }
}

// ---------------------------------------------------------------------------
// Kernel 2: persistent recurrence (R3 barrier structure, proven correct).
//   Phase 1: CTA (kc,jt): partial[kc][b][jt*64+j] = sum_{k in kc chunk} h[b][k]*Whh[k][j]
//   Phase 2: h_t[b][j] = tanh(xproj[b][t][j] + sum_kc partial)
// Changes vs R3:
//   - Whh slice (32KB) persists in smem for all 512 steps.
//   - fp32x2 FFMA2 math: thread tile 2 rows x 8 cols, acc in packed f32x2.
//   - sh[64][64] unpadded, XOR-(row&7) column swizzle -> conflict-free reads.
//   Static smem = 16KB + 32KB = 49152B (exactly the 48KB static limit).
// ---------------------------------------------------------------------------
__global__ void __launch_bounds__(256) rnn_kernel(const float* __restrict__ h0,
                                                  const float* __restrict__ Whh)
{
    __shared__ float sh[64][64];        // 16KB  h tile [b][k], cols XOR-swizzled by (b&7)
    __shared__ float sw[2][64][64];     // 32KB  Whh slice, persistent across steps

    const int tid = threadIdx.x;
    const int bx  = blockIdx.x;
    const int kc  = bx >> 4;            // 0..7  (K chunk of 128)
    const int jt  = bx & 15;            // 0..15 (64-column tile)
    const int tx  = tid & 7;            // 8 col-groups of 8 columns
    const int ty  = tid >> 3;           // 32 row-groups of 2 rows

    // Preload Whh slice once (rows kc*128..+127, cols jt*64..+63).
    #pragma unroll
    for (int ks = 0; ks < 2; ++ks)
        #pragma unroll
        for (int i = 0; i < 4; ++i) {
            int idx = tid + i * 256;
            int kk = idx >> 4, j4 = (idx & 15) * 4;
            float4 v = *(const float4*)(Whh + (size_t)(kc * 128 + ks * 64 + kk) * HH + jt * 64 + j4);
            *(float4*)&sw[ks][kk][j4] = v;
        }
    __syncthreads();

    const int r0 = ty * 2;              // this thread's 2 output rows
    const int j0 = jt * 64 + tx * 8;    // this thread's 8 output cols (global)

    for (int t = 0; t < TT; ++t) {
        const float* hb;
        size_t bstr;
        if (t == 0) { hb = h0;                          bstr = HH; }
        else        { hb = g_hs + (size_t)(t - 1) * HH; bstr = (size_t)TT * HH; }

        unsigned long long acc[2][4] = {};   // [row][jpair] packed f32x2 (0 == {0,0})

        #pragma unroll
        for (int ks = 0; ks < 2; ++ks) {
            const int K0 = kc * 128 + ks * 64;
            // stage h tile: 64 b-rows x 64 k, XOR-swizzled columns
            #pragma unroll
            for (int i = 0; i < 4; ++i) {
                int idx = tid + i * 256;
                int bb = idx >> 4, c = idx & 15;                 // c = float4 column
                float4 v = __ldcg((const float4*)(hb + (size_t)bb * bstr + K0 + c * 4));
                *(float4*)&sh[bb][((c ^ (bb & 7)) << 2)] = v;
            }
            __syncthreads();
            #pragma unroll 4
            for (int k = 0; k < 64; k += 4) {
                const int c4 = k >> 2;
                float4 a0 = *(const float4*)&sh[r0    ][((c4 ^ ( r0      & 7)) << 2)];
                float4 a1 = *(const float4*)&sh[r0 + 1][((c4 ^ ((r0 + 1) & 7)) << 2)];
                const float a0v[4] = {a0.x, a0.y, a0.z, a0.w};
                const float a1v[4] = {a1.x, a1.y, a1.z, a1.w};
                #pragma unroll
                for (int kk = 0; kk < 4; ++kk) {
                    F4U w0, w1;
                    w0.f = *(const float4*)&sw[ks][k + kk][tx * 8];
                    w1.f = *(const float4*)&sw[ks][k + kk][tx * 8 + 4];
                    unsigned long long s0 = splat2(a0v[kk]);
                    unsigned long long s1 = splat2(a1v[kk]);
                    ffma2(acc[0][0], s0, w0.u[0]);
                    ffma2(acc[0][1], s0, w0.u[1]);
                    ffma2(acc[0][2], s0, w1.u[0]);
                    ffma2(acc[0][3], s0, w1.u[1]);
                    ffma2(acc[1][0], s1, w0.u[0]);
                    ffma2(acc[1][1], s1, w0.u[1]);
                    ffma2(acc[1][2], s1, w1.u[0]);
                    ffma2(acc[1][3], s1, w1.u[1]);
                }
            }
            __syncthreads();
        }

        // publish split-K partials
        {
            float* pp = g_partial + (size_t)kc * (BB * HH);
            #pragma unroll
            for (int i = 0; i < 2; ++i) {
                F4U lo, hi;
                lo.u[0] = acc[i][0]; lo.u[1] = acc[i][1];
                hi.u[0] = acc[i][2]; hi.u[1] = acc[i][3];
                *(float4*)&pp[((r0 + i) << 10) + (j0 & 1023)]     = lo.f;
                *(float4*)&pp[((r0 + i) << 10) + (j0 & 1023) + 4] = hi.f;
            }
        }

        gbar();

        // Phase 2: reduce 8 partials + xproj, tanh, write h_t (R3-proven mapping).
        #pragma unroll
        for (int r = 0; r < 2; ++r) {
            int o = bx * 512 + r * 256 + tid;   // 0..65535, j-contiguous
            int b = o >> 10, j = o & 1023;
            float s = g_xproj[((size_t)b * TT + t) * HH + j];
            #pragma unroll
            for (int c = 0; c < 8; ++c)
                s += __ldcg(&g_partial[((c * 64 + b) << 10) + j]);
            g_hs[((size_t)b * TT + t) * HH + j] = tanhf(s);
        }

        gbar();
    }
}

// ---------------------------------------------------------------------------
// Kernel 3: logits[r][v] = sum_k hs[r][k] * Wl[v][k] + bl[v]  (unchanged)
// ---------------------------------------------------------------------------
__global__ void __launch_bounds__(256) logits_kernel(const float* __restrict__ Wl,
                                                     const float* __restrict__ bl,
                                                     float* __restrict__ out)
{
    __shared__ float sa [64][36];
    __shared__ float swl[32][100];

    const int tid = threadIdx.x;
    const int tx  = tid & 15;
    const int ty  = tid >> 4;
    const size_t row0 = (size_t)blockIdx.x * 64;
    const int v0  = tx * 6;

    float acc[4][6] = {};

    #pragma unroll 1
    for (int K0 = 0; K0 < HH; K0 += 32) {
        #pragma unroll
        for (int i = 0; i < 2; ++i) {
            int idx = tid + i * 256;
            int r = idx >> 3, k4 = (idx & 7) * 4;
            float4 v = *(const float4*)(g_hs + (row0 + r) * HH + K0 + k4);
            *(float4*)&sa[r][k4] = v;
        }
        #pragma unroll
        for (int i = 0; i < 3; ++i) {
            int idx = tid + i * 256;
            int vv = idx >> 3, k4 = (idx & 7) * 4;
            float4 v = *(const float4*)(Wl + (size_t)vv * HH + K0 + k4);
            swl[k4 + 0][vv] = v.x;
            swl[k4 + 1][vv] = v.y;
            swl[k4 + 2][vv] = v.z;
            swl[k4 + 3][vv] = v.w;
        }
        __syncthreads();
        #pragma unroll 4
        for (int k = 0; k < 32; ++k) {
            float a0 = sa[ty * 4 + 0][k];
            float a1 = sa[ty * 4 + 1][k];
            float a2 = sa[ty * 4 + 2][k];
            float a3 = sa[ty * 4 + 3][k];
            #pragma unroll
            for (int j = 0; j < 6; ++j) {
                float w = swl[k][v0 + j];
                acc[0][j] += a0 * w;
                acc[1][j] += a1 * w;
                acc[2][j] += a2 * w;
                acc[3][j] += a3 * w;
            }
        }
        __syncthreads();
    }

    #pragma unroll
    for (int i = 0; i < 4; ++i)
        #pragma unroll
        for (int j = 0; j < 6; ++j)
            out[(row0 + ty * 4 + i) * VV + v0 + j] = acc[i][j] + bl[v0 + j];
}

// ---------------------------------------------------------------------------
// Kernel 4: h_last = hs[:, T-1, :]
// ---------------------------------------------------------------------------
__global__ void __launch_bounds__(256) hlast_kernel(float* __restrict__ out)
{
    int i = blockIdx.x * 256 + threadIdx.x;
    int b = i >> 10, j = i & 1023;
    out[i] = g_hs[((size_t)b * TT + (TT - 1)) * HH + j];
}

// ---------------------------------------------------------------------------
extern "C" void kernel_launch(void* const* d_in, const int* in_sizes, int n_in,
                              void* d_out, int out_size)
{
    const float* x   = (const float*)d_in[0];
    const float* h0  = (const float*)d_in[1];
    const float* Wxh = (const float*)d_in[2];
    const float* Whh = (const float*)d_in[3];
    const float* bh  = (const float*)d_in[4];
    const float* Wl  = (const float*)d_in[5];
    const float* bl  = (const float*)d_in[6];
    float* out = (float*)d_out;
    (void)in_sizes; (void)n_in;

    xproj_kernel <<<dim3(16, (BB * TT) / 64), 256>>>(x, Wxh, bh);
    rnn_kernel   <<<NCTA, 256>>>(h0, Whh);
    logits_kernel<<<(BB * TT) / 64, 256>>>(Wl, bl, out);

    const size_t logits_elems = (size_t)BB * TT * VV;
    if ((size_t)out_size >= logits_elems + (size_t)BB * HH)
        hlast_kernel<<<(BB * HH) / 256, 256>>>(out + logits_elems);
}

// round 6
// speedup vs baseline: 1.5617x; 1.5617x over previous
#include <cuda_runtime.h>

// Problem constants (fixed by the reference).
#define BB   64
#define TT   512
#define VV   96
#define HH   1024
#define NCTA 128   // 8 k-chunks x 16 column tiles, co-resident (1 CTA/SM, 48KB smem)

// ---------------------------------------------------------------------------
// Scratch (device globals: allocation-free per harness rules)
// ---------------------------------------------------------------------------
__device__ float g_xproj[(size_t)BB * TT * HH];     // x @ Wxh + bh, [b][t][h]
__device__ float g_hs   [(size_t)BB * TT * HH];     // hidden states, [b][t][h]
__device__ float g_partial[8 * BB * HH];            // split-K partials [kc][b][j]
__device__ unsigned g_cnt = 0;
__device__ volatile unsigned g_gen = 0;

// ---------------------------------------------------------------------------
// Global software barrier — EXACTLY the R3-proven version (incl. nanosleep).
// ---------------------------------------------------------------------------
__device__ __forceinline__ void gbar()
{
    __syncthreads();
    if (threadIdx.x == 0) {
        __threadfence();                      // release prior global stores
        unsigned g = g_gen;
        if (atomicAdd(&g_cnt, 1u) == NCTA - 1) {
            g_cnt = 0;
            __threadfence();
            g_gen = g + 1;
        } else {
            while (g_gen == g) { __nanosleep(64); }
        }
        __threadfence();                      // acquire
    }
    __syncthreads();
}

// ---------------------------------------------------------------------------
// Kernel 1: xproj[r][j] = sum_v x[r][v] * Wxh[v][j] + bh[j]   (unchanged, R3)
// ---------------------------------------------------------------------------
__global__ void __launch_bounds__(256) xproj_kernel(const float* __restrict__ x,
                                                    const float* __restrict__ Wxh,
                                                    const float* __restrict__ bh)
{
    __shared__ float sa[64][36];
    __shared__ float sw[32][64];

    const int tid = threadIdx.x;
    const int tx  = tid & 15;
    const int ty  = tid >> 4;
    const size_t row0 = (size_t)blockIdx.y * 64;
    const int jt  = blockIdx.x;

    float acc[4][4] = {};

    #pragma unroll 1
    for (int K0 = 0; K0 < 96; K0 += 32) {
        #pragma unroll
        for (int i = 0; i < 2; ++i) {
            int idx = tid + i * 256;
            int r = idx >> 3, k4 = (idx & 7) * 4;
            float4 v = *(const float4*)(x + (row0 + r) * 96 + K0 + k4);
            *(float4*)&sa[r][k4] = v;
        }
        #pragma unroll
        for (int i = 0; i < 2; ++i) {
            int idx = tid + i * 256;
            int kk = idx >> 4, j4 = (idx & 15) * 4;
            float4 v = *(const float4*)(Wxh + (size_t)(K0 + kk) * HH + jt * 64 + j4);
            *(float4*)&sw[kk][j4] = v;
        }
        __syncthreads();
        #pragma unroll 4
        for (int k = 0; k < 32; k += 4) {
            float ha[4][4], wa[4][4];
            #pragma unroll
            for (int i = 0; i < 4; ++i) {
                float4 v = *(const float4*)&sa[ty * 4 + i][k];
                ha[i][0] = v.x; ha[i][1] = v.y; ha[i][2] = v.z; ha[i][3] = v.w;
            }
            #pragma unroll
            for (int kk = 0; kk < 4; ++kk) {
                float4 v = *(const float4*)&sw[k + kk][tx * 4];
                wa[kk][0] = v.x; wa[kk][1] = v.y; wa[kk][2] = v.z; wa[kk][3] = v.w;
            }
            #pragma unroll
            for (int kk = 0; kk < 4; ++kk)
                #pragma unroll
                for (int i = 0; i < 4; ++i)
                    #pragma unroll
                    for (int j = 0; j < 4; ++j)
                        acc[i][j] += ha[i][kk] * wa[kk][j];
        }
        __syncthreads();
    }

    float4 bv = *(const float4*)(bh + jt * 64 + tx * 4);
    #pragma unroll
    for (int i = 0; i < 4; ++i) {
        float4 v = make_float4(acc[i][0] + bv.x, acc[i][1] + bv.y,
                               acc[i][2] + bv.z, acc[i][3] + bv.w);
        *(float4*)&g_xproj[(row0 + ty * 4 + i) * HH + jt * 64 + tx * 4] = v;
    }
}

// ---------------------------------------------------------------------------
// Kernel 2: persistent recurrence. R3 schedule + math (scalar FFMA, proven).
// Changes vs R3 (all local):
//   - Whh slice persistent in smem (sw[2][64][64], 32KB) — loaded once.
//   - sh[64][64] unpadded with XOR-(row&7) float4 column swizzle (R5-proven).
//   - ks=1 h-slice prefetched into registers during ks=0 compute.
//   - phase-2 xproj reads prefetched before the first barrier.
// Static smem = 16KB + 32KB = 49152B.
// ---------------------------------------------------------------------------
__global__ void __launch_bounds__(256) rnn_kernel(const float* __restrict__ h0,
                                                  const float* __restrict__ Whh)
{
    __shared__ float sh[64][64];        // h tile [b][k], float4 cols XOR-swizzled by (b&7)
    __shared__ float sw[2][64][64];     // Whh slice, persistent across all steps

    const int tid = threadIdx.x;
    const int bx  = blockIdx.x;
    const int kc  = bx >> 4;            // 0..7  (K chunk of 128)
    const int jt  = bx & 15;            // 0..15 (64-column tile)
    const int tx  = tid & 15;
    const int ty  = tid >> 4;

    // Preload Whh slice once (rows kc*128..+127, cols jt*64..+63).
    #pragma unroll
    for (int ks = 0; ks < 2; ++ks)
        #pragma unroll
        for (int i = 0; i < 4; ++i) {
            int idx = tid + i * 256;
            int kk = idx >> 4, j4 = (idx & 15) * 4;
            float4 v = *(const float4*)(Whh + (size_t)(kc * 128 + ks * 64 + kk) * HH + jt * 64 + j4);
            *(float4*)&sw[ks][kk][j4] = v;
        }
    __syncthreads();

    // Per-thread staging coordinates (same for every step).
    const int s_bb = tid >> 4;               // row written by this thread (i=0 slice)
    const int s_c  = tid & 15;               // float4 column

    for (int t = 0; t < TT; ++t) {
        const float* hb;
        size_t bstr;
        if (t == 0) { hb = h0;                          bstr = HH; }
        else        { hb = g_hs + (size_t)(t - 1) * HH; bstr = (size_t)TT * HH; }

        // ---- issue ks=0 loads ----
        float4 ra[4];
        #pragma unroll
        for (int i = 0; i < 4; ++i) {
            int idx = tid + i * 256;
            int bb = idx >> 4, c = idx & 15;
            ra[i] = __ldcg((const float4*)(hb + (size_t)bb * bstr + kc * 128 + c * 4));
        }
        // ---- prefetch phase-2 xproj (read-only, independent) ----
        float xp[2];
        #pragma unroll
        for (int r = 0; r < 2; ++r) {
            int o = bx * 512 + r * 256 + tid;
            int b = o >> 10, j = o & 1023;
            xp[r] = __ldcg(&g_xproj[((size_t)b * TT + t) * HH + j]);
        }

        float acc[4][4] = {};

        // ---- stage ks=0 ----
        #pragma unroll
        for (int i = 0; i < 4; ++i) {
            int idx = tid + i * 256;
            int bb = idx >> 4, c = idx & 15;
            *(float4*)&sh[bb][((c ^ (bb & 7)) << 2)] = ra[i];
        }
        __syncthreads();

        // ---- prefetch ks=1 into registers ----
        float4 rb[4];
        #pragma unroll
        for (int i = 0; i < 4; ++i) {
            int idx = tid + i * 256;
            int bb = idx >> 4, c = idx & 15;
            rb[i] = __ldcg((const float4*)(hb + (size_t)bb * bstr + kc * 128 + 64 + c * 4));
        }

        // ---- compute ks=0 ----
        #pragma unroll 4
        for (int k = 0; k < 64; k += 4) {
            const int c4 = k >> 2;
            float ha[4][4], wa[4][4];
            #pragma unroll
            for (int i = 0; i < 4; ++i) {
                int row = ty * 4 + i;
                float4 v = *(const float4*)&sh[row][((c4 ^ (row & 7)) << 2)];
                ha[i][0] = v.x; ha[i][1] = v.y; ha[i][2] = v.z; ha[i][3] = v.w;
            }
            #pragma unroll
            for (int kk = 0; kk < 4; ++kk) {
                float4 v = *(const float4*)&sw[0][k + kk][tx * 4];
                wa[kk][0] = v.x; wa[kk][1] = v.y; wa[kk][2] = v.z; wa[kk][3] = v.w;
            }
            #pragma unroll
            for (int kk = 0; kk < 4; ++kk)
                #pragma unroll
                for (int i = 0; i < 4; ++i)
                    #pragma unroll
                    for (int j = 0; j < 4; ++j)
                        acc[i][j] += ha[i][kk] * wa[kk][j];
        }
        __syncthreads();

        // ---- stage ks=1 ----
        #pragma unroll
        for (int i = 0; i < 4; ++i) {
            int idx = tid + i * 256;
            int bb = idx >> 4, c = idx & 15;
            *(float4*)&sh[bb][((c ^ (bb & 7)) << 2)] = rb[i];
        }
        __syncthreads();

        // ---- compute ks=1 ----
        #pragma unroll 4
        for (int k = 0; k < 64; k += 4) {
            const int c4 = k >> 2;
            float ha[4][4], wa[4][4];
            #pragma unroll
            for (int i = 0; i < 4; ++i) {
                int row = ty * 4 + i;
                float4 v = *(const float4*)&sh[row][((c4 ^ (row & 7)) << 2)];
                ha[i][0] = v.x; ha[i][1] = v.y; ha[i][2] = v.z; ha[i][3] = v.w;
            }
            #pragma unroll
            for (int kk = 0; kk < 4; ++kk) {
                float4 v = *(const float4*)&sw[1][k + kk][tx * 4];
                wa[kk][0] = v.x; wa[kk][1] = v.y; wa[kk][2] = v.z; wa[kk][3] = v.w;
            }
            #pragma unroll
            for (int kk = 0; kk < 4; ++kk)
                #pragma unroll
                for (int i = 0; i < 4; ++i)
                    #pragma unroll
                    for (int j = 0; j < 4; ++j)
                        acc[i][j] += ha[i][kk] * wa[kk][j];
        }

        // ---- publish split-K partials (R3 layout) ----
        {
            float* pp = g_partial + (size_t)kc * (BB * HH);
            #pragma unroll
            for (int i = 0; i < 4; ++i) {
                int b = ty * 4 + i;
                float4 v = make_float4(acc[i][0], acc[i][1], acc[i][2], acc[i][3]);
                *(float4*)&pp[(b << 10) + jt * 64 + tx * 4] = v;
            }
        }

        gbar();

        // ---- phase 2: reduce 8 partials + prefetched xproj, tanh (R3 mapping) ----
        #pragma unroll
        for (int r = 0; r < 2; ++r) {
            int o = bx * 512 + r * 256 + tid;
            int b = o >> 10, j = o & 1023;
            float s = xp[r];
            #pragma unroll
            for (int c = 0; c < 8; ++c)
                s += __ldcg(&g_partial[((c * 64 + b) << 10) + j]);
            g_hs[((size_t)b * TT + t) * HH + j] = tanhf(s);
        }

        gbar();
    }
}

// ---------------------------------------------------------------------------
// Kernel 3: logits[r][v] = sum_k hs[r][k] * Wl[v][k] + bl[v]  (unchanged, R3)
// ---------------------------------------------------------------------------
__global__ void __launch_bounds__(256) logits_kernel(const float* __restrict__ Wl,
                                                     const float* __restrict__ bl,
                                                     float* __restrict__ out)
{
    __shared__ float sa [64][36];
    __shared__ float swl[32][100];

    const int tid = threadIdx.x;
    const int tx  = tid & 15;
    const int ty  = tid >> 4;
    const size_t row0 = (size_t)blockIdx.x * 64;
    const int v0  = tx * 6;

    float acc[4][6] = {};

    #pragma unroll 1
    for (int K0 = 0; K0 < HH; K0 += 32) {
        #pragma unroll
        for (int i = 0; i < 2; ++i) {
            int idx = tid + i * 256;
            int r = idx >> 3, k4 = (idx & 7) * 4;
            float4 v = *(const float4*)(g_hs + (row0 + r) * HH + K0 + k4);
            *(float4*)&sa[r][k4] = v;
        }
        #pragma unroll
        for (int i = 0; i < 3; ++i) {
            int idx = tid + i * 256;
            int vv = idx >> 3, k4 = (idx & 7) * 4;
            float4 v = *(const float4*)(Wl + (size_t)vv * HH + K0 + k4);
            swl[k4 + 0][vv] = v.x;
            swl[k4 + 1][vv] = v.y;
            swl[k4 + 2][vv] = v.z;
            swl[k4 + 3][vv] = v.w;
        }
        __syncthreads();
        #pragma unroll 4
        for (int k = 0; k < 32; ++k) {
            float a0 = sa[ty * 4 + 0][k];
            float a1 = sa[ty * 4 + 1][k];
            float a2 = sa[ty * 4 + 2][k];
            float a3 = sa[ty * 4 + 3][k];
            #pragma unroll
            for (int j = 0; j < 6; ++j) {
                float w = swl[k][v0 + j];
                acc[0][j] += a0 * w;
                acc[1][j] += a1 * w;
                acc[2][j] += a2 * w;
                acc[3][j] += a3 * w;
            }
        }
        __syncthreads();
    }

    #pragma unroll
    for (int i = 0; i < 4; ++i)
        #pragma unroll
        for (int j = 0; j < 6; ++j)
            out[(row0 + ty * 4 + i) * VV + v0 + j] = acc[i][j] + bl[v0 + j];
}

// ---------------------------------------------------------------------------
// Kernel 4: h_last = hs[:, T-1, :]
// ---------------------------------------------------------------------------
__global__ void __launch_bounds__(256) hlast_kernel(float* __restrict__ out)
{
    int i = blockIdx.x * 256 + threadIdx.x;
    int b = i >> 10, j = i & 1023;
    out[i] = g_hs[((size_t)b * TT + (TT - 1)) * HH + j];
}

// ---------------------------------------------------------------------------
extern "C" void kernel_launch(void* const* d_in, const int* in_sizes, int n_in,
                              void* d_out, int out_size)
{
    const float* x   = (const float*)d_in[0];
    const float* h0  = (const float*)d_in[1];
    const float* Wxh = (const float*)d_in[2];
    const float* Whh = (const float*)d_in[3];
    const float* bh  = (const float*)d_in[4];
    const float* Wl  = (const float*)d_in[5];
    const float* bl  = (const float*)d_in[6];
    float* out = (float*)d_out;
    (void)in_sizes; (void)n_in;

    xproj_kernel <<<dim3(16, (BB * TT) / 64), 256>>>(x, Wxh, bh);
    rnn_kernel   <<<NCTA, 256>>>(h0, Whh);
    logits_kernel<<<(BB * TT) / 64, 256>>>(Wl, bl, out);

    const size_t logits_elems = (size_t)BB * TT * VV;
    if ((size_t)out_size >= logits_elems + (size_t)BB * HH)
        hlast_kernel<<<(BB * HH) / 256, 256>>>(out + logits_elems);
}